// round 14
// baseline (speedup 1.0000x reference)
#include <cuda_runtime.h>
#include <cuda_bf16.h>
#include <cstddef>

// Problem constants
#define Bc 2
#define Sc 2048
#define Ec 1024
#define Hc 16
#define Dc 64
#define M_TOT (Bc*Sc)

// Scratch (device globals)
__device__ float g_qh[(size_t)Bc*Hc*Sc*Dc];            // [b,h,s,d] tf32, pre-scaled by 1/8
__device__ float g_kh[(size_t)Bc*Hc*Sc*Dc];            // [b,h,s,d] tf32
__device__ __nv_bfloat16 g_vhi[(size_t)Bc*Hc*Sc*Dc];   // V hi (bf16 split)
__device__ __nv_bfloat16 g_vlo[(size_t)Bc*Hc*Sc*Dc];   // V lo
__device__ float g_ctx[(size_t)Bc*Sc*Ec];              // [b,s,h*d]
__device__ float g_tmp[(size_t)Bc*Sc*Ec];              // pre-LN output
__device__ float g_l[(size_t)Bc*Hc*Sc];                // per-row 1/sum

// ---------------- helpers ----------------
__device__ __forceinline__ void bf16mma(float c[4], const unsigned a[4],
                                        unsigned b0, unsigned b1)
{
    asm volatile(
        "mma.sync.aligned.m16n8k16.row.col.f32.bf16.bf16.f32 "
        "{%0,%1,%2,%3}, {%4,%5,%6,%7}, {%8,%9}, {%0,%1,%2,%3};\n"
        : "+f"(c[0]), "+f"(c[1]), "+f"(c[2]), "+f"(c[3])
        : "r"(a[0]), "r"(a[1]), "r"(a[2]), "r"(a[3]), "r"(b0), "r"(b1));
}

__device__ __forceinline__ void tf32mma(float c[4], const unsigned a[4],
                                        unsigned b0, unsigned b1)
{
    asm volatile(
        "mma.sync.aligned.m16n8k8.row.col.f32.tf32.tf32.f32 "
        "{%0,%1,%2,%3}, {%4,%5,%6,%7}, {%8,%9}, {%0,%1,%2,%3};\n"
        : "+f"(c[0]), "+f"(c[1]), "+f"(c[2]), "+f"(c[3])
        : "r"(a[0]), "r"(a[1]), "r"(a[2]), "r"(a[3]), "r"(b0), "r"(b1));
}

__device__ __forceinline__ unsigned cvt_tf32(float x)
{
    unsigned r;
    asm("cvt.rna.tf32.f32 %0, %1;" : "=r"(r) : "f"(x));
    return r;
}

__device__ __forceinline__ void split2pack(float a, float b, unsigned& hi, unsigned& lo)
{
    __nv_bfloat16 ha = __float2bfloat16(a), hb = __float2bfloat16(b);
    __nv_bfloat16 la = __float2bfloat16(a - __bfloat162float(ha));
    __nv_bfloat16 lb = __float2bfloat16(b - __bfloat162float(hb));
    hi = (unsigned)__bfloat16_as_ushort(ha) | ((unsigned)__bfloat16_as_ushort(hb) << 16);
    lo = (unsigned)__bfloat16_as_ushort(la) | ((unsigned)__bfloat16_as_ushort(lb) << 16);
}

__device__ __forceinline__ void ldmx4t(unsigned addr, unsigned r[4])
{
    asm volatile("ldmatrix.sync.aligned.m8n8.x4.trans.shared.b16 {%0,%1,%2,%3}, [%4];"
                 : "=r"(r[0]), "=r"(r[1]), "=r"(r[2]), "=r"(r[3]) : "r"(addr));
}

__device__ __forceinline__ void cpasync16(unsigned s, const void* g)
{
    asm volatile("cp.async.cg.shared.global [%0], [%1], 16;\n" :: "r"(s), "l"(g));
}
#define CP_COMMIT() asm volatile("cp.async.commit_group;\n" ::: "memory")
#define CP_WAIT(n)  asm volatile("cp.async.wait_group %0;\n" :: "n"(n) : "memory")

// ---------------------------------------------------------------------------
// tf32 GEMM core v2: BM=256, BN=128, BK=32; 256 threads, 8 warps (4x2),
// warp tile 64x64 (mt=4, nt=8) -> MMA:LDS = 1.0. cp.async double-buffered,
// raw-bit tf32 fragments. MODE 0: head-permuted writes; MODE 1: row-major.
// ---------------------------------------------------------------------------
#define GA_ST 36
#define GW_ST 136
#define G_SZA (256*GA_ST*4)
#define G_SZW (32*GW_ST*4)
#define GEMM_SMEM (2*G_SZA + 2*G_SZW)

template<int MODE>
__device__ __forceinline__ void gemm_core(char* gsm,
                                          const float* __restrict__ A,
                                          const float* __restrict__ W,
                                          const float* __restrict__ bias,
                                          int outsel, int bx, int by)
{
    const unsigned sb = (unsigned)__cvta_generic_to_shared(gsm);
    const unsigned* sA = (const unsigned*)gsm;
    const unsigned* sW = (const unsigned*)(gsm + 2*G_SZA);

    const int tid  = threadIdx.x;
    const int crow = by * 256;
    const int ccol = bx * 128;

    const int warp = tid >> 5, lane = tid & 31;
    const int wm0 = (warp >> 1) * 64;      // 0,64,128,192
    const int wn0 = (warp & 1) * 64;
    const int gid = lane >> 2;
    const int qid = lane & 3;

    float acc[4][8][4];
#pragma unroll
    for (int mt = 0; mt < 4; mt++)
#pragma unroll
        for (int nt = 0; nt < 8; nt++)
#pragma unroll
            for (int e = 0; e < 4; e++) acc[mt][nt][e] = 0.f;

    auto issueA = [&](int t, int buf) {
        const float* Ag = A + (size_t)crow * 1024 + t * 32;
        const unsigned sbA = sb + buf * G_SZA;
#pragma unroll
        for (int j = 0; j < 8; j++) {
            const int c = tid + j * 256;
            const int row = c >> 3, col = (c & 7) * 4;
            cpasync16(sbA + (row * GA_ST + col) * 4, Ag + (size_t)row * 1024 + col);
        }
    };
    auto issueW = [&](int t, int buf) {
        const float* Wg = W + (size_t)t * 32 * 1024 + ccol;
        const unsigned sbW = sb + 2*G_SZA + buf * G_SZW;
#pragma unroll
        for (int j = 0; j < 4; j++) {
            const int c = tid + j * 256;
            const int row = c >> 5, col = (c & 31) * 4;
            cpasync16(sbW + (row * GW_ST + col) * 4, Wg + (size_t)row * 1024 + col);
        }
    };

    issueA(0, 0); issueW(0, 0); CP_COMMIT();

    for (int t = 0; t < 32; t++) {
        if (t + 1 < 32) {
            issueA(t + 1, (t + 1) & 1);
            issueW(t + 1, (t + 1) & 1);
            CP_COMMIT();
            CP_WAIT(1);
        } else {
            CP_WAIT(0);
        }
        __syncthreads();

        const unsigned* At = sA + (t & 1) * (G_SZA / 4);
        const unsigned* Wt = sW + (t & 1) * (G_SZW / 4);

#pragma unroll
        for (int ks = 0; ks < 4; ks++) {
            unsigned a[4][4];
#pragma unroll
            for (int mt = 0; mt < 4; mt++) {
                const unsigned* p = At + (wm0 + mt * 16 + gid) * GA_ST + ks * 8;
                a[mt][0] = p[qid];
                a[mt][1] = p[8 * GA_ST + qid];
                a[mt][2] = p[qid + 4];
                a[mt][3] = p[8 * GA_ST + qid + 4];
            }
#pragma unroll
            for (int nt = 0; nt < 8; nt++) {
                const int n = wn0 + nt * 8 + gid;
                const unsigned b0 = Wt[(ks * 8 + qid) * GW_ST + n];
                const unsigned b1 = Wt[(ks * 8 + qid + 4) * GW_ST + n];
#pragma unroll
                for (int mt = 0; mt < 4; mt++)
                    tf32mma(acc[mt][nt], a[mt], b0, b1);
            }
        }
        __syncthreads();
    }

    const float qscale = (MODE == 0 && outsel == 0) ? 0.125f : 1.0f;
#pragma unroll
    for (int mt = 0; mt < 4; mt++) {
#pragma unroll
        for (int nt = 0; nt < 8; nt++) {
            const int row = crow + wm0 + mt * 16 + gid;
            const int col = ccol + wn0 + nt * 8 + 2 * qid;
            const float b0 = bias[col], b1 = bias[col + 1];
            float2 v0, v1;
            v0.x = acc[mt][nt][0] + b0; v0.y = acc[mt][nt][1] + b1;
            v1.x = acc[mt][nt][2] + b0; v1.y = acc[mt][nt][3] + b1;
            if (MODE == 1) {
                *(float2*)(g_tmp + (size_t)row * 1024 + col) = v0;
                *(float2*)(g_tmp + (size_t)(row + 8) * 1024 + col) = v1;
            } else {
                const int bb = row >> 11, hh = col >> 6, d = col & 63;
                const int s = row & 2047;
                const size_t base = ((((size_t)bb * Hc + hh) * Sc + s) << 6) + d;
                if (outsel == 2) {
                    unsigned hi, lo;
                    split2pack(v0.x, v0.y, hi, lo);
                    *(unsigned*)&g_vhi[base] = hi;
                    *(unsigned*)&g_vlo[base] = lo;
                    split2pack(v1.x, v1.y, hi, lo);
                    *(unsigned*)&g_vhi[base + (8 << 6)] = hi;
                    *(unsigned*)&g_vlo[base + (8 << 6)] = lo;
                } else {
                    float* out = outsel ? g_kh : g_qh;
                    float2 w0, w1;
                    w0.x = __uint_as_float(cvt_tf32(v0.x * qscale));
                    w0.y = __uint_as_float(cvt_tf32(v0.y * qscale));
                    w1.x = __uint_as_float(cvt_tf32(v1.x * qscale));
                    w1.y = __uint_as_float(cvt_tf32(v1.y * qscale));
                    *(float2*)(out + base) = w0;
                    *(float2*)(out + base + (8 << 6)) = w1;
                }
            }
        }
    }
}

__global__ void __launch_bounds__(256) gemm_qkv(const float* __restrict__ q,
                                                const float* __restrict__ k,
                                                const float* __restrict__ v,
                                                const float* __restrict__ Wq,
                                                const float* __restrict__ bq,
                                                const float* __restrict__ Wk,
                                                const float* __restrict__ bk,
                                                const float* __restrict__ Wv,
                                                const float* __restrict__ bv)
{
    extern __shared__ char gsm[];
    const int sel = blockIdx.z;
    const float* A    = (sel == 0) ? q  : (sel == 1) ? k  : v;
    const float* W    = (sel == 0) ? Wq : (sel == 1) ? Wk : Wv;
    const float* bias = (sel == 0) ? bq : (sel == 1) ? bk : bv;
    gemm_core<0>(gsm, A, W, bias, sel, blockIdx.x, blockIdx.y);
}

__global__ void __launch_bounds__(256) gemm_out(const float* __restrict__ Wo,
                                                const float* __restrict__ bo)
{
    extern __shared__ char gsm[];
    gemm_core<1>(gsm, g_ctx, Wo, bo, 3, blockIdx.x, blockIdx.y);
}

// ---------------------------------------------------------------------------
// Attention PASS A: sums + ctx (+ store 1/l to g_l). 256 threads, 8 warps x
// 32 rows; tf32 QK, bf16 3-term E@V from C-frags, causal skipping.
// ---------------------------------------------------------------------------
#define QSTf 68
#define KSTf 68
#define VSTB 72
#define OFF_Q 0
#define SZ_Q   (256*QSTf*4)
#define OFF_K  (OFF_Q + SZ_Q)
#define SZ_K1  (128*KSTf*4)
#define OFF_VH (OFF_K + 2*SZ_K1)
#define SZ_V1B (128*VSTB*2)
#define ATTN_SMEM  (OFF_VH + 4*SZ_V1B)
#define ATTNB_SMEM (OFF_K + 2*SZ_K1)

__global__ void __launch_bounds__(256, 1) attn_passA(const int* __restrict__ isM)
{
    extern __shared__ char smraw[];
    const unsigned sbase = (unsigned)__cvta_generic_to_shared(smraw);
    const unsigned* Qs = (const unsigned*)(smraw + OFF_Q);
    const unsigned* Ks = (const unsigned*)(smraw + OFF_K);

    const int tid = threadIdx.x;
    const int masked = *isM;
    const int i0 = (masked ? (gridDim.x - 1 - blockIdx.x) : blockIdx.x) * 256;
    const int h  = blockIdx.y;
    const int b  = blockIdx.z;

    const int warp = tid >> 5, lane = tid & 31;
    const int gid = lane >> 2, qid = lane & 3;
    const int grp = lane >> 3, li = lane & 7;

    const size_t bh = (size_t)b * Hc + h;
    const float* Qg = g_qh + bh * Sc * Dc + (size_t)i0 * Dc;
    const float* Kg = g_kh + bh * Sc * Dc;
    const __nv_bfloat16* Vhg = g_vhi + bh * Sc * Dc;
    const __nv_bfloat16* Vlg = g_vlo + bh * Sc * Dc;

    const int jmax = masked ? (i0 + 256) : Sc;
    const int ntiles = jmax >> 7;

    const unsigned offV = (unsigned)(((li + ((grp & 1) << 3)) * VSTB + ((grp >> 1) << 3)) * 2);

#pragma unroll
    for (int t = 0; t < 16; t++) {
        const int c = tid + t * 256;
        const int row = c >> 4, col4 = (c & 15) * 4;
        cpasync16(sbase + OFF_Q + (row * QSTf + col4) * 4, Qg + row * 64 + col4);
    }
#pragma unroll
    for (int t = 0; t < 8; t++) {
        const int c = tid + t * 256;
        const int row = c >> 4, col4 = (c & 15) * 4;
        cpasync16(sbase + OFF_K + (row * KSTf + col4) * 4, Kg + row * 64 + col4);
    }
#pragma unroll
    for (int t = 0; t < 4; t++) {
        const int c = tid + t * 256;
        const int row = c >> 3, col8 = (c & 7) * 8;
        cpasync16(sbase + OFF_VH + (row * VSTB + col8) * 2, Vhg + row * 64 + col8);
        cpasync16(sbase + OFF_VH + SZ_V1B + (row * VSTB + col8) * 2, Vlg + row * 64 + col8);
    }
    CP_COMMIT();

    float oacc[2][8][4];
#pragma unroll
    for (int mt = 0; mt < 2; mt++)
#pragma unroll
        for (int nt = 0; nt < 8; nt++)
#pragma unroll
            for (int e = 0; e < 4; e++) oacc[mt][nt][e] = 0.f;
    float lpa[4] = {0.f, 0.f, 0.f, 0.f};

    const int r0w = warp * 32;
    const int rmaxw = i0 + r0w + 31;

    for (int t = 0; t < ntiles; t++) {
        const int jt = t << 7;
        if (t + 1 < ntiles) {
            const float* Kn = Kg + (size_t)(jt + 128) * 64;
            const __nv_bfloat16* Vhn = Vhg + (size_t)(jt + 128) * 64;
            const __nv_bfloat16* Vln = Vlg + (size_t)(jt + 128) * 64;
            const unsigned kb = OFF_K + ((t + 1) & 1) * SZ_K1;
            const unsigned vb = OFF_VH + ((t + 1) & 1) * 2 * SZ_V1B;
#pragma unroll
            for (int tt = 0; tt < 8; tt++) {
                const int c = tid + tt * 256;
                const int row = c >> 4, col4 = (c & 15) * 4;
                cpasync16(sbase + kb + (row * KSTf + col4) * 4, Kn + row * 64 + col4);
            }
#pragma unroll
            for (int tt = 0; tt < 4; tt++) {
                const int c = tid + tt * 256;
                const int row = c >> 3, col8 = (c & 7) * 8;
                cpasync16(sbase + vb + (row * VSTB + col8) * 2, Vhn + row * 64 + col8);
                cpasync16(sbase + vb + SZ_V1B + (row * VSTB + col8) * 2, Vln + row * 64 + col8);
            }
            CP_COMMIT();
            CP_WAIT(1);
        } else {
            CP_WAIT(0);
        }
        __syncthreads();

        const unsigned* Kt = Ks + (t & 1) * (SZ_K1 / 4);
        const unsigned vh_s = sbase + OFF_VH + (t & 1) * 2 * SZ_V1B;
        const unsigned vl_s = vh_s + SZ_V1B;

#pragma unroll
        for (int half = 0; half < 2; half++) {
            if (masked && (jt + half * 64) > rmaxw) continue;

            float sacc[2][8][4];
#pragma unroll
            for (int mt = 0; mt < 2; mt++)
#pragma unroll
                for (int nt = 0; nt < 8; nt++)
#pragma unroll
                    for (int e = 0; e < 4; e++) sacc[mt][nt][e] = 0.f;

#pragma unroll
            for (int ks = 0; ks < 8; ks++) {
                unsigned qa[2][4];
#pragma unroll
                for (int mt = 0; mt < 2; mt++) {
                    const unsigned* q0 = Qs + (r0w + mt * 16 + gid) * QSTf + ks * 8;
                    qa[mt][0] = q0[qid];            qa[mt][1] = q0[8 * QSTf + qid];
                    qa[mt][2] = q0[qid + 4];        qa[mt][3] = q0[8 * QSTf + qid + 4];
                }
#pragma unroll
                for (int nt = 0; nt < 8; nt++) {
                    const unsigned* kr = Kt + (half * 64 + nt * 8 + gid) * KSTf + ks * 8;
                    const unsigned b0 = kr[qid], b1 = kr[qid + 4];
                    tf32mma(sacc[0][nt], qa[0], b0, b1);
                    tf32mma(sacc[1][nt], qa[1], b0, b1);
                }
            }

#pragma unroll
            for (int c = 0; c < 4; c++) {
                unsigned aEh[2][4], aEl[2][4];
#pragma unroll
                for (int mt = 0; mt < 2; mt++) {
                    const int row0 = i0 + r0w + mt * 16 + gid;
                    const int row1 = row0 + 8;
                    const int jc0 = jt + half * 64 + c * 16 + 2 * qid;
                    const int jc1 = jc0 + 8;
                    float s00 = sacc[mt][2*c][0],   s01 = sacc[mt][2*c][1];
                    float s10 = sacc[mt][2*c][2],   s11 = sacc[mt][2*c][3];
                    float f00 = sacc[mt][2*c+1][0], f01 = sacc[mt][2*c+1][1];
                    float f10 = sacc[mt][2*c+1][2], f11 = sacc[mt][2*c+1][3];
                    if (masked) {
                        if (jc0     > row0) s00 = -1e9f;
                        if (jc0 + 1 > row0) s01 = -1e9f;
                        if (jc0     > row1) s10 = -1e9f;
                        if (jc0 + 1 > row1) s11 = -1e9f;
                        if (jc1     > row0) f00 = -1e9f;
                        if (jc1 + 1 > row0) f01 = -1e9f;
                        if (jc1     > row1) f10 = -1e9f;
                        if (jc1 + 1 > row1) f11 = -1e9f;
                    }
                    const float e00 = __expf(s00), e01 = __expf(s01);
                    const float e10 = __expf(s10), e11 = __expf(s11);
                    const float g00 = __expf(f00), g01 = __expf(f01);
                    const float g10 = __expf(f10), g11 = __expf(f11);
                    lpa[mt*2]     += e00 + e01 + g00 + g01;
                    lpa[mt*2 + 1] += e10 + e11 + g10 + g11;
                    split2pack(e00, e01, aEh[mt][0], aEl[mt][0]);
                    split2pack(e10, e11, aEh[mt][1], aEl[mt][1]);
                    split2pack(g00, g01, aEh[mt][2], aEl[mt][2]);
                    split2pack(g10, g11, aEh[mt][3], aEl[mt][3]);
                }
#pragma unroll
                for (int ntp = 0; ntp < 4; ntp++) {
                    unsigned vbH[4], vbL[4];
                    const unsigned voff = (unsigned)((half * 64 + c * 16) * VSTB * 2 + ntp * 32) + offV;
                    ldmx4t(vh_s + voff, vbH);
                    ldmx4t(vl_s + voff, vbL);
#pragma unroll
                    for (int mt = 0; mt < 2; mt++) {
                        bf16mma(oacc[mt][2*ntp],   aEh[mt], vbH[0], vbH[1]);
                        bf16mma(oacc[mt][2*ntp],   aEh[mt], vbL[0], vbL[1]);
                        bf16mma(oacc[mt][2*ntp],   aEl[mt], vbH[0], vbH[1]);
                        bf16mma(oacc[mt][2*ntp+1], aEh[mt], vbH[2], vbH[3]);
                        bf16mma(oacc[mt][2*ntp+1], aEh[mt], vbL[2], vbL[3]);
                        bf16mma(oacc[mt][2*ntp+1], aEl[mt], vbH[2], vbH[3]);
                    }
                }
            }
        }
        __syncthreads();
    }

    float inv[4];
#pragma unroll
    for (int r = 0; r < 4; r++) {
        float s = lpa[r];
        s += __shfl_xor_sync(0xffffffffu, s, 1);
        s += __shfl_xor_sync(0xffffffffu, s, 2);
        inv[r] = 1.f / s;
    }
    if (qid == 0) {
#pragma unroll
        for (int mt = 0; mt < 2; mt++) {
            g_l[bh * Sc + i0 + r0w + mt*16 + gid]     = inv[mt*2];
            g_l[bh * Sc + i0 + r0w + mt*16 + gid + 8] = inv[mt*2 + 1];
        }
    }
    {
        float* ctx = g_ctx + ((size_t)b * Sc) * Ec + (size_t)h * Dc;
#pragma unroll
        for (int mt = 0; mt < 2; mt++) {
            const int row0 = i0 + r0w + mt * 16 + gid;
            const float iv0 = inv[mt*2], iv1 = inv[mt*2 + 1];
#pragma unroll
            for (int nt = 0; nt < 8; nt++) {
                const int col = nt * 8 + 2 * qid;
                float2 v0, v1;
                v0.x = oacc[mt][nt][0] * iv0; v0.y = oacc[mt][nt][1] * iv0;
                v1.x = oacc[mt][nt][2] * iv1; v1.y = oacc[mt][nt][3] * iv1;
                *(float2*)(ctx + (size_t)row0 * Ec + col) = v0;
                *(float2*)(ctx + (size_t)(row0 + 8) * Ec + col) = v1;
            }
        }
    }
}

// ---------------------------------------------------------------------------
// Attention PASS B (fork stream): recompute S, write normalized attn +
// causal zero-fill. Reads 1/l from g_l.
// ---------------------------------------------------------------------------
__global__ void __launch_bounds__(256, 1) attn_passB(const int* __restrict__ isM,
                                                     float* __restrict__ attn_out)
{
    extern __shared__ char smraw[];
    const unsigned sbase = (unsigned)__cvta_generic_to_shared(smraw);
    const unsigned* Qs = (const unsigned*)(smraw + OFF_Q);
    const unsigned* Ks = (const unsigned*)(smraw + OFF_K);

    const int tid = threadIdx.x;
    const int masked = *isM;
    const int i0 = (masked ? (gridDim.x - 1 - blockIdx.x) : blockIdx.x) * 256;
    const int h  = blockIdx.y;
    const int b  = blockIdx.z;

    const int warp = tid >> 5, lane = tid & 31;
    const int gid = lane >> 2, qid = lane & 3;

    const size_t bh = (size_t)b * Hc + h;
    const float* Qg = g_qh + bh * Sc * Dc + (size_t)i0 * Dc;
    const float* Kg = g_kh + bh * Sc * Dc;

    const int jmax = masked ? (i0 + 256) : Sc;
    const int ntiles = jmax >> 7;

#pragma unroll
    for (int t = 0; t < 16; t++) {
        const int c = tid + t * 256;
        const int row = c >> 4, col4 = (c & 15) * 4;
        cpasync16(sbase + OFF_Q + (row * QSTf + col4) * 4, Qg + row * 64 + col4);
    }
#pragma unroll
    for (int t = 0; t < 8; t++) {
        const int c = tid + t * 256;
        const int row = c >> 4, col4 = (c & 15) * 4;
        cpasync16(sbase + OFF_K + (row * KSTf + col4) * 4, Kg + row * 64 + col4);
    }
    CP_COMMIT();

    const int r0w = warp * 32;
    const int rmaxw = i0 + r0w + 31;

    float inv[4];
#pragma unroll
    for (int mt = 0; mt < 2; mt++) {
        inv[mt*2]     = g_l[bh * Sc + i0 + r0w + mt*16 + gid];
        inv[mt*2 + 1] = g_l[bh * Sc + i0 + r0w + mt*16 + gid + 8];
    }

    for (int t = 0; t < ntiles; t++) {
        const int jt = t << 7;
        if (t + 1 < ntiles) {
            const float* Kn = Kg + (size_t)(jt + 128) * 64;
            const unsigned kb = OFF_K + ((t + 1) & 1) * SZ_K1;
#pragma unroll
            for (int tt = 0; tt < 8; tt++) {
                const int c = tid + tt * 256;
                const int row = c >> 4, col4 = (c & 15) * 4;
                cpasync16(sbase + kb + (row * KSTf + col4) * 4, Kn + row * 64 + col4);
            }
            CP_COMMIT();
            CP_WAIT(1);
        } else {
            CP_WAIT(0);
        }
        __syncthreads();

        const unsigned* Kt = Ks + (t & 1) * (SZ_K1 / 4);

#pragma unroll
        for (int half = 0; half < 2; half++) {
            if (masked && (jt + half * 64) > rmaxw) {
                const float2 z = {0.f, 0.f};
#pragma unroll
                for (int mt = 0; mt < 2; mt++) {
                    const int row0 = i0 + r0w + mt * 16 + gid;
                    const int row1 = row0 + 8;
#pragma unroll
                    for (int nt = 0; nt < 8; nt++) {
                        const int jc = jt + half * 64 + nt * 8 + 2 * qid;
                        *(float2*)(attn_out + (bh * Sc + row0) * Sc + jc) = z;
                        *(float2*)(attn_out + (bh * Sc + row1) * Sc + jc) = z;
                    }
                }
                continue;
            }

            float sacc[2][8][4];
#pragma unroll
            for (int mt = 0; mt < 2; mt++)
#pragma unroll
                for (int nt = 0; nt < 8; nt++)
#pragma unroll
                    for (int e = 0; e < 4; e++) sacc[mt][nt][e] = 0.f;

#pragma unroll
            for (int ks = 0; ks < 8; ks++) {
                unsigned qa[2][4];
#pragma unroll
                for (int mt = 0; mt < 2; mt++) {
                    const unsigned* q0 = Qs + (r0w + mt * 16 + gid) * QSTf + ks * 8;
                    qa[mt][0] = q0[qid];            qa[mt][1] = q0[8 * QSTf + qid];
                    qa[mt][2] = q0[qid + 4];        qa[mt][3] = q0[8 * QSTf + qid + 4];
                }
#pragma unroll
                for (int nt = 0; nt < 8; nt++) {
                    const unsigned* kr = Kt + (half * 64 + nt * 8 + gid) * KSTf + ks * 8;
                    const unsigned b0 = kr[qid], b1 = kr[qid + 4];
                    tf32mma(sacc[0][nt], qa[0], b0, b1);
                    tf32mma(sacc[1][nt], qa[1], b0, b1);
                }
            }

#pragma unroll
            for (int nt = 0; nt < 8; nt++) {
#pragma unroll
                for (int mt = 0; mt < 2; mt++) {
                    const int row0 = i0 + r0w + mt * 16 + gid;
                    const int row1 = row0 + 8;
                    const int jc = jt + half * 64 + nt * 8 + 2 * qid;
                    float s0 = sacc[mt][nt][0];
                    float s1 = sacc[mt][nt][1];
                    float s2 = sacc[mt][nt][2];
                    float s3 = sacc[mt][nt][3];
                    if (masked) {
                        if (jc     > row0) s0 = -1e9f;
                        if (jc + 1 > row0) s1 = -1e9f;
                        if (jc     > row1) s2 = -1e9f;
                        if (jc + 1 > row1) s3 = -1e9f;
                    }
                    const float iv0 = inv[mt*2], iv1 = inv[mt*2 + 1];
                    float2 w0, w1;
                    w0.x = __expf(s0) * iv0; w0.y = __expf(s1) * iv0;
                    w1.x = __expf(s2) * iv1; w1.y = __expf(s3) * iv1;
                    *(float2*)(attn_out + (bh * Sc + row0) * Sc + jc) = w0;
                    *(float2*)(attn_out + (bh * Sc + row1) * Sc + jc) = w1;
                }
            }
        }
        __syncthreads();
    }

    if (masked && jmax < Sc) {
        const int ncols = Sc - jmax;
        const float4 z = {0.f, 0.f, 0.f, 0.f};
        for (int r = warp; r < 256; r += 8) {
            float* rowp = attn_out + (bh * Sc + i0 + r) * Sc + jmax;
            for (int cz = lane * 4; cz < ncols; cz += 128)
                *(float4*)(rowp + cz) = z;
        }
    }
}

// ---------------------------------------------------------------------------
// Residual + LayerNorm
// ---------------------------------------------------------------------------
__global__ void __launch_bounds__(256) ln_kernel(const float* __restrict__ qin,
                                                 float* __restrict__ out)
{
    const size_t row = blockIdx.x;
    const int tid = threadIdx.x;
    float4 x  = *(const float4*)(g_tmp + row * 1024 + tid * 4);
    float4 qq = *(const float4*)(qin   + row * 1024 + tid * 4);
    x.x += qq.x; x.y += qq.y; x.z += qq.z; x.w += qq.w;

    float s  = x.x + x.y + x.z + x.w;
    float s2 = x.x*x.x + x.y*x.y + x.z*x.z + x.w*x.w;

    __shared__ float rs[8], rs2[8];
    const int w = tid >> 5, lane = tid & 31;
#pragma unroll
    for (int o = 16; o; o >>= 1) {
        s  += __shfl_xor_sync(0xffffffffu, s,  o);
        s2 += __shfl_xor_sync(0xffffffffu, s2, o);
    }
    if (!lane) { rs[w] = s; rs2[w] = s2; }
    __syncthreads();
    if (w == 0) {
        float a  = (lane < 8) ? rs[lane]  : 0.f;
        float a2 = (lane < 8) ? rs2[lane] : 0.f;
#pragma unroll
        for (int o = 4; o; o >>= 1) {
            a  += __shfl_xor_sync(0xffffffffu, a,  o);
            a2 += __shfl_xor_sync(0xffffffffu, a2, o);
        }
        if (!lane) { rs[0] = a; rs2[0] = a2; }
    }
    __syncthreads();
    const float mu   = rs[0] * (1.f / 1024.f);
    const float var  = rs2[0] * (1.f / 1024.f) - mu * mu;
    const float rstd = rsqrtf(var + 1e-5f);
    float4 o;
    o.x = (x.x - mu) * rstd; o.y = (x.y - mu) * rstd;
    o.z = (x.z - mu) * rstd; o.w = (x.w - mu) * rstd;
    *(float4*)(out + row * 1024 + tid * 4) = o;
}

// ---------------------------------------------------------------------------
extern "C" void kernel_launch(void* const* d_in, const int* in_sizes, int n_in,
                              void* d_out, int out_size)
{
    (void)in_sizes; (void)n_in; (void)out_size;
    const float* q  = (const float*)d_in[0];
    const float* k  = (const float*)d_in[1];
    const float* v  = (const float*)d_in[2];
    const float* Wq = (const float*)d_in[3];
    const float* bq = (const float*)d_in[4];
    const float* Wk = (const float*)d_in[5];
    const float* bk = (const float*)d_in[6];
    const float* Wv = (const float*)d_in[7];
    const float* bv = (const float*)d_in[8];
    const float* Wo = (const float*)d_in[9];
    const float* bo = (const float*)d_in[10];
    const int*   isM = (const int*)d_in[11];

    float* out  = (float*)d_out;
    float* attn = out + (size_t)Bc * Sc * Ec;

    cudaFuncSetAttribute(attn_passA,
                         cudaFuncAttributeMaxDynamicSharedMemorySize, ATTN_SMEM);
    cudaFuncSetAttribute(attn_passB,
                         cudaFuncAttributeMaxDynamicSharedMemorySize, ATTNB_SMEM);
    cudaFuncSetAttribute(gemm_qkv,
                         cudaFuncAttributeMaxDynamicSharedMemorySize, GEMM_SMEM);
    cudaFuncSetAttribute(gemm_out,
                         cudaFuncAttributeMaxDynamicSharedMemorySize, GEMM_SMEM);

    // fork-join resources (host objects, no device memory; created during capture)
    cudaStream_t s2;
    cudaEvent_t e1, e2;
    cudaStreamCreateWithFlags(&s2, cudaStreamNonBlocking);
    cudaEventCreateWithFlags(&e1, cudaEventDisableTiming);
    cudaEventCreateWithFlags(&e2, cudaEventDisableTiming);

    dim3 gqkv(Ec / 128, M_TOT / 256, 3);
    gemm_qkv<<<gqkv, 256, GEMM_SMEM>>>(q, k, v, Wq, bq, Wk, bk, Wv, bv);

    attn_passA<<<dim3(Sc / 256, Hc, Bc), 256, ATTN_SMEM>>>(isM);

    // fork: passB (DRAM-bound) overlaps gemm_out + ln (tensor-bound)
    cudaEventRecord(e1, 0);
    cudaStreamWaitEvent(s2, e1, 0);
    attn_passB<<<dim3(Sc / 256, Hc, Bc), 256, ATTNB_SMEM, s2>>>(isM, attn);

    dim3 gg(Ec / 128, M_TOT / 256);
    gemm_out<<<gg, 256, GEMM_SMEM>>>(Wo, bo);
    ln_kernel<<<M_TOT, 256>>>(q, out);

    // join
    cudaEventRecord(e2, s2);
    cudaStreamWaitEvent(0, e2, 0);
}

// round 15
// speedup vs baseline: 1.0358x; 1.0358x over previous
#include <cuda_runtime.h>
#include <cuda_bf16.h>
#include <cstddef>

// Problem constants
#define Bc 2
#define Sc 2048
#define Ec 1024
#define Hc 16
#define Dc 64
#define M_TOT (Bc*Sc)

// Scratch (device globals)
__device__ float g_qh[(size_t)Bc*Hc*Sc*Dc];            // [b,h,s,d] tf32, pre-scaled by 1/8
__device__ float g_kh[(size_t)Bc*Hc*Sc*Dc];            // [b,h,s,d] tf32
__device__ __nv_bfloat16 g_vhi[(size_t)Bc*Hc*Sc*Dc];   // V hi (bf16 split)
__device__ __nv_bfloat16 g_vlo[(size_t)Bc*Hc*Sc*Dc];   // V lo
__device__ float g_ctx[(size_t)Bc*Sc*Ec];              // [b,s,h*d]
__device__ float g_tmp[(size_t)Bc*Sc*Ec];              // pre-LN output
__device__ float g_l[(size_t)Bc*Hc*Sc];                // per-row 1/sum

// ---------------- helpers ----------------
__device__ __forceinline__ void bf16mma(float c[4], const unsigned a[4],
                                        unsigned b0, unsigned b1)
{
    asm volatile(
        "mma.sync.aligned.m16n8k16.row.col.f32.bf16.bf16.f32 "
        "{%0,%1,%2,%3}, {%4,%5,%6,%7}, {%8,%9}, {%0,%1,%2,%3};\n"
        : "+f"(c[0]), "+f"(c[1]), "+f"(c[2]), "+f"(c[3])
        : "r"(a[0]), "r"(a[1]), "r"(a[2]), "r"(a[3]), "r"(b0), "r"(b1));
}

__device__ __forceinline__ void tf32mma(float c[4], const unsigned a[4],
                                        unsigned b0, unsigned b1)
{
    asm volatile(
        "mma.sync.aligned.m16n8k8.row.col.f32.tf32.tf32.f32 "
        "{%0,%1,%2,%3}, {%4,%5,%6,%7}, {%8,%9}, {%0,%1,%2,%3};\n"
        : "+f"(c[0]), "+f"(c[1]), "+f"(c[2]), "+f"(c[3])
        : "r"(a[0]), "r"(a[1]), "r"(a[2]), "r"(a[3]), "r"(b0), "r"(b1));
}

__device__ __forceinline__ unsigned cvt_tf32(float x)
{
    unsigned r;
    asm("cvt.rna.tf32.f32 %0, %1;" : "=r"(r) : "f"(x));
    return r;
}

__device__ __forceinline__ void split2pack(float a, float b, unsigned& hi, unsigned& lo)
{
    __nv_bfloat16 ha = __float2bfloat16(a), hb = __float2bfloat16(b);
    __nv_bfloat16 la = __float2bfloat16(a - __bfloat162float(ha));
    __nv_bfloat16 lb = __float2bfloat16(b - __bfloat162float(hb));
    hi = (unsigned)__bfloat16_as_ushort(ha) | ((unsigned)__bfloat16_as_ushort(hb) << 16);
    lo = (unsigned)__bfloat16_as_ushort(la) | ((unsigned)__bfloat16_as_ushort(lb) << 16);
}

__device__ __forceinline__ void ldmx4t(unsigned addr, unsigned r[4])
{
    asm volatile("ldmatrix.sync.aligned.m8n8.x4.trans.shared.b16 {%0,%1,%2,%3}, [%4];"
                 : "=r"(r[0]), "=r"(r[1]), "=r"(r[2]), "=r"(r[3]) : "r"(addr));
}

__device__ __forceinline__ void cpasync16(unsigned s, const void* g)
{
    asm volatile("cp.async.cg.shared.global [%0], [%1], 16;\n" :: "r"(s), "l"(g));
}
#define CP_COMMIT() asm volatile("cp.async.commit_group;\n" ::: "memory")
#define CP_WAIT(n)  asm volatile("cp.async.wait_group %0;\n" :: "n"(n) : "memory")

// ---------------------------------------------------------------------------
// tf32 GEMM core (R13 proven): BM=128 BN=128 BK=32, 256 threads, 8 warps
// (4x2), warp 32x64, cp.async double-buffered, raw-bit tf32 fragments.
// ---------------------------------------------------------------------------
#define GA_ST 36
#define GW_ST 136
#define G_SZA (128*GA_ST*4)
#define G_SZW (32*GW_ST*4)
#define GEMM_SMEM (2*G_SZA + 2*G_SZW)

template<int MODE>
__device__ __forceinline__ void gemm_core(char* gsm,
                                          const float* __restrict__ A,
                                          const float* __restrict__ W,
                                          const float* __restrict__ bias,
                                          int outsel, int bx, int by)
{
    const unsigned sb = (unsigned)__cvta_generic_to_shared(gsm);
    const unsigned* sA = (const unsigned*)gsm;
    const unsigned* sW = (const unsigned*)(gsm + 2*G_SZA);

    const int tid  = threadIdx.x;
    const int crow = by * 128;
    const int ccol = bx * 128;

    const int warp = tid >> 5, lane = tid & 31;
    const int wm0 = (warp >> 1) * 32;
    const int wn0 = (warp & 1) * 64;
    const int gid = lane >> 2;
    const int qid = lane & 3;

    float acc[2][8][4];
#pragma unroll
    for (int mt = 0; mt < 2; mt++)
#pragma unroll
        for (int nt = 0; nt < 8; nt++)
#pragma unroll
            for (int e = 0; e < 4; e++) acc[mt][nt][e] = 0.f;

    auto issueA = [&](int t, int buf) {
        const float* Ag = A + (size_t)crow * 1024 + t * 32;
        const unsigned sbA = sb + buf * G_SZA;
#pragma unroll
        for (int j = 0; j < 4; j++) {
            const int c = tid + j * 256;
            const int row = c >> 3, col = (c & 7) * 4;
            cpasync16(sbA + (row * GA_ST + col) * 4, Ag + (size_t)row * 1024 + col);
        }
    };
    auto issueW = [&](int t, int buf) {
        const float* Wg = W + (size_t)t * 32 * 1024 + ccol;
        const unsigned sbW = sb + 2*G_SZA + buf * G_SZW;
#pragma unroll
        for (int j = 0; j < 4; j++) {
            const int c = tid + j * 256;
            const int row = c >> 5, col = (c & 31) * 4;
            cpasync16(sbW + (row * GW_ST + col) * 4, Wg + (size_t)row * 1024 + col);
        }
    };

    issueA(0, 0); issueW(0, 0); CP_COMMIT();

    for (int t = 0; t < 32; t++) {
        if (t + 1 < 32) {
            issueA(t + 1, (t + 1) & 1);
            issueW(t + 1, (t + 1) & 1);
            CP_COMMIT();
            CP_WAIT(1);
        } else {
            CP_WAIT(0);
        }
        __syncthreads();

        const unsigned* At = sA + (t & 1) * (G_SZA / 4);
        const unsigned* Wt = sW + (t & 1) * (G_SZW / 4);

#pragma unroll
        for (int ks = 0; ks < 4; ks++) {
            unsigned a[2][4];
#pragma unroll
            for (int mt = 0; mt < 2; mt++) {
                const unsigned* p = At + (wm0 + mt * 16 + gid) * GA_ST + ks * 8;
                a[mt][0] = p[qid];
                a[mt][1] = p[8 * GA_ST + qid];
                a[mt][2] = p[qid + 4];
                a[mt][3] = p[8 * GA_ST + qid + 4];
            }
#pragma unroll
            for (int nt = 0; nt < 8; nt++) {
                const int n = wn0 + nt * 8 + gid;
                const unsigned b0 = Wt[(ks * 8 + qid) * GW_ST + n];
                const unsigned b1 = Wt[(ks * 8 + qid + 4) * GW_ST + n];
                tf32mma(acc[0][nt], a[0], b0, b1);
                tf32mma(acc[1][nt], a[1], b0, b1);
            }
        }
        __syncthreads();
    }

    const float qscale = (MODE == 0 && outsel == 0) ? 0.125f : 1.0f;
#pragma unroll
    for (int mt = 0; mt < 2; mt++) {
#pragma unroll
        for (int nt = 0; nt < 8; nt++) {
            const int row = crow + wm0 + mt * 16 + gid;
            const int col = ccol + wn0 + nt * 8 + 2 * qid;
            const float b0 = bias[col], b1 = bias[col + 1];
            float2 v0, v1;
            v0.x = acc[mt][nt][0] + b0; v0.y = acc[mt][nt][1] + b1;
            v1.x = acc[mt][nt][2] + b0; v1.y = acc[mt][nt][3] + b1;
            if (MODE == 1) {
                *(float2*)(g_tmp + (size_t)row * 1024 + col) = v0;
                *(float2*)(g_tmp + (size_t)(row + 8) * 1024 + col) = v1;
            } else {
                const int bb = row >> 11, hh = col >> 6, d = col & 63;
                const int s = row & 2047;
                const size_t base = ((((size_t)bb * Hc + hh) * Sc + s) << 6) + d;
                if (outsel == 2) {
                    unsigned hi, lo;
                    split2pack(v0.x, v0.y, hi, lo);
                    *(unsigned*)&g_vhi[base] = hi;
                    *(unsigned*)&g_vlo[base] = lo;
                    split2pack(v1.x, v1.y, hi, lo);
                    *(unsigned*)&g_vhi[base + (8 << 6)] = hi;
                    *(unsigned*)&g_vlo[base + (8 << 6)] = lo;
                } else {
                    float* out = outsel ? g_kh : g_qh;
                    float2 w0, w1;
                    w0.x = __uint_as_float(cvt_tf32(v0.x * qscale));
                    w0.y = __uint_as_float(cvt_tf32(v0.y * qscale));
                    w1.x = __uint_as_float(cvt_tf32(v1.x * qscale));
                    w1.y = __uint_as_float(cvt_tf32(v1.y * qscale));
                    *(float2*)(out + base) = w0;
                    *(float2*)(out + base + (8 << 6)) = w1;
                }
            }
        }
    }
}

__global__ void __launch_bounds__(256) gemm_qkv(const float* __restrict__ q,
                                                const float* __restrict__ k,
                                                const float* __restrict__ v,
                                                const float* __restrict__ Wq,
                                                const float* __restrict__ bq,
                                                const float* __restrict__ Wk,
                                                const float* __restrict__ bk,
                                                const float* __restrict__ Wv,
                                                const float* __restrict__ bv)
{
    extern __shared__ char gsm[];
    const int sel = blockIdx.z;
    const float* A    = (sel == 0) ? q  : (sel == 1) ? k  : v;
    const float* W    = (sel == 0) ? Wq : (sel == 1) ? Wk : Wv;
    const float* bias = (sel == 0) ? bq : (sel == 1) ? bk : bv;
    gemm_core<0>(gsm, A, W, bias, sel, blockIdx.x, blockIdx.y);
}

__global__ void __launch_bounds__(256) gemm_out(const float* __restrict__ Wo,
                                                const float* __restrict__ bo)
{
    extern __shared__ char gsm[];
    gemm_core<1>(gsm, g_ctx, Wo, bo, 3, blockIdx.x, blockIdx.y);
}

// ---------------------------------------------------------------------------
// Attention PASS A (R13): 256 rows/block, 8 warps x 32 rows; tf32 QK,
// bf16 3-term E@V from C-frags, causal skipping; writes ctx + 1/l.
// ---------------------------------------------------------------------------
#define QSTf 68
#define KSTf 68
#define VSTB 72
#define OFF_Q 0
#define SZ_Q   (256*QSTf*4)
#define OFF_K  (OFF_Q + SZ_Q)
#define SZ_K1  (128*KSTf*4)
#define OFF_VH (OFF_K + 2*SZ_K1)
#define SZ_V1B (128*VSTB*2)
#define ATTN_SMEM  (OFF_VH + 4*SZ_V1B)

// passB: 128 rows/block for 2 CTAs/SM
#define SZ_QB   (128*QSTf*4)
#define OFFB_K  (SZ_QB)
#define ATTNB_SMEM (OFFB_K + 2*SZ_K1)

__global__ void __launch_bounds__(256, 1) attn_passA(const int* __restrict__ isM)
{
    extern __shared__ char smraw[];
    const unsigned sbase = (unsigned)__cvta_generic_to_shared(smraw);
    const unsigned* Qs = (const unsigned*)(smraw + OFF_Q);
    const unsigned* Ks = (const unsigned*)(smraw + OFF_K);

    const int tid = threadIdx.x;
    const int masked = *isM;
    const int i0 = (masked ? (gridDim.x - 1 - blockIdx.x) : blockIdx.x) * 256;
    const int h  = blockIdx.y;
    const int b  = blockIdx.z;

    const int warp = tid >> 5, lane = tid & 31;
    const int gid = lane >> 2, qid = lane & 3;
    const int grp = lane >> 3, li = lane & 7;

    const size_t bh = (size_t)b * Hc + h;
    const float* Qg = g_qh + bh * Sc * Dc + (size_t)i0 * Dc;
    const float* Kg = g_kh + bh * Sc * Dc;
    const __nv_bfloat16* Vhg = g_vhi + bh * Sc * Dc;
    const __nv_bfloat16* Vlg = g_vlo + bh * Sc * Dc;

    const int jmax = masked ? (i0 + 256) : Sc;
    const int ntiles = jmax >> 7;

    const unsigned offV = (unsigned)(((li + ((grp & 1) << 3)) * VSTB + ((grp >> 1) << 3)) * 2);

#pragma unroll
    for (int t = 0; t < 16; t++) {
        const int c = tid + t * 256;
        const int row = c >> 4, col4 = (c & 15) * 4;
        cpasync16(sbase + OFF_Q + (row * QSTf + col4) * 4, Qg + row * 64 + col4);
    }
#pragma unroll
    for (int t = 0; t < 8; t++) {
        const int c = tid + t * 256;
        const int row = c >> 4, col4 = (c & 15) * 4;
        cpasync16(sbase + OFF_K + (row * KSTf + col4) * 4, Kg + row * 64 + col4);
    }
#pragma unroll
    for (int t = 0; t < 4; t++) {
        const int c = tid + t * 256;
        const int row = c >> 3, col8 = (c & 7) * 8;
        cpasync16(sbase + OFF_VH + (row * VSTB + col8) * 2, Vhg + row * 64 + col8);
        cpasync16(sbase + OFF_VH + SZ_V1B + (row * VSTB + col8) * 2, Vlg + row * 64 + col8);
    }
    CP_COMMIT();

    float oacc[2][8][4];
#pragma unroll
    for (int mt = 0; mt < 2; mt++)
#pragma unroll
        for (int nt = 0; nt < 8; nt++)
#pragma unroll
            for (int e = 0; e < 4; e++) oacc[mt][nt][e] = 0.f;
    float lpa[4] = {0.f, 0.f, 0.f, 0.f};

    const int r0w = warp * 32;
    const int rmaxw = i0 + r0w + 31;

    for (int t = 0; t < ntiles; t++) {
        const int jt = t << 7;
        if (t + 1 < ntiles) {
            const float* Kn = Kg + (size_t)(jt + 128) * 64;
            const __nv_bfloat16* Vhn = Vhg + (size_t)(jt + 128) * 64;
            const __nv_bfloat16* Vln = Vlg + (size_t)(jt + 128) * 64;
            const unsigned kb = OFF_K + ((t + 1) & 1) * SZ_K1;
            const unsigned vb = OFF_VH + ((t + 1) & 1) * 2 * SZ_V1B;
#pragma unroll
            for (int tt = 0; tt < 8; tt++) {
                const int c = tid + tt * 256;
                const int row = c >> 4, col4 = (c & 15) * 4;
                cpasync16(sbase + kb + (row * KSTf + col4) * 4, Kn + row * 64 + col4);
            }
#pragma unroll
            for (int tt = 0; tt < 4; tt++) {
                const int c = tid + tt * 256;
                const int row = c >> 3, col8 = (c & 7) * 8;
                cpasync16(sbase + vb + (row * VSTB + col8) * 2, Vhn + row * 64 + col8);
                cpasync16(sbase + vb + SZ_V1B + (row * VSTB + col8) * 2, Vln + row * 64 + col8);
            }
            CP_COMMIT();
            CP_WAIT(1);
        } else {
            CP_WAIT(0);
        }
        __syncthreads();

        const unsigned* Kt = Ks + (t & 1) * (SZ_K1 / 4);
        const unsigned vh_s = sbase + OFF_VH + (t & 1) * 2 * SZ_V1B;
        const unsigned vl_s = vh_s + SZ_V1B;

#pragma unroll
        for (int half = 0; half < 2; half++) {
            if (masked && (jt + half * 64) > rmaxw) continue;

            float sacc[2][8][4];
#pragma unroll
            for (int mt = 0; mt < 2; mt++)
#pragma unroll
                for (int nt = 0; nt < 8; nt++)
#pragma unroll
                    for (int e = 0; e < 4; e++) sacc[mt][nt][e] = 0.f;

#pragma unroll
            for (int ks = 0; ks < 8; ks++) {
                unsigned qa[2][4];
#pragma unroll
                for (int mt = 0; mt < 2; mt++) {
                    const unsigned* q0 = Qs + (r0w + mt * 16 + gid) * QSTf + ks * 8;
                    qa[mt][0] = q0[qid];            qa[mt][1] = q0[8 * QSTf + qid];
                    qa[mt][2] = q0[qid + 4];        qa[mt][3] = q0[8 * QSTf + qid + 4];
                }
#pragma unroll
                for (int nt = 0; nt < 8; nt++) {
                    const unsigned* kr = Kt + (half * 64 + nt * 8 + gid) * KSTf + ks * 8;
                    const unsigned b0 = kr[qid], b1 = kr[qid + 4];
                    tf32mma(sacc[0][nt], qa[0], b0, b1);
                    tf32mma(sacc[1][nt], qa[1], b0, b1);
                }
            }

#pragma unroll
            for (int c = 0; c < 4; c++) {
                unsigned aEh[2][4], aEl[2][4];
#pragma unroll
                for (int mt = 0; mt < 2; mt++) {
                    const int row0 = i0 + r0w + mt * 16 + gid;
                    const int row1 = row0 + 8;
                    const int jc0 = jt + half * 64 + c * 16 + 2 * qid;
                    const int jc1 = jc0 + 8;
                    float s00 = sacc[mt][2*c][0],   s01 = sacc[mt][2*c][1];
                    float s10 = sacc[mt][2*c][2],   s11 = sacc[mt][2*c][3];
                    float f00 = sacc[mt][2*c+1][0], f01 = sacc[mt][2*c+1][1];
                    float f10 = sacc[mt][2*c+1][2], f11 = sacc[mt][2*c+1][3];
                    if (masked) {
                        if (jc0     > row0) s00 = -1e9f;
                        if (jc0 + 1 > row0) s01 = -1e9f;
                        if (jc0     > row1) s10 = -1e9f;
                        if (jc0 + 1 > row1) s11 = -1e9f;
                        if (jc1     > row0) f00 = -1e9f;
                        if (jc1 + 1 > row0) f01 = -1e9f;
                        if (jc1     > row1) f10 = -1e9f;
                        if (jc1 + 1 > row1) f11 = -1e9f;
                    }
                    const float e00 = __expf(s00), e01 = __expf(s01);
                    const float e10 = __expf(s10), e11 = __expf(s11);
                    const float g00 = __expf(f00), g01 = __expf(f01);
                    const float g10 = __expf(f10), g11 = __expf(f11);
                    lpa[mt*2]     += e00 + e01 + g00 + g01;
                    lpa[mt*2 + 1] += e10 + e11 + g10 + g11;
                    split2pack(e00, e01, aEh[mt][0], aEl[mt][0]);
                    split2pack(e10, e11, aEh[mt][1], aEl[mt][1]);
                    split2pack(g00, g01, aEh[mt][2], aEl[mt][2]);
                    split2pack(g10, g11, aEh[mt][3], aEl[mt][3]);
                }
#pragma unroll
                for (int ntp = 0; ntp < 4; ntp++) {
                    unsigned vbH[4], vbL[4];
                    const unsigned voff = (unsigned)((half * 64 + c * 16) * VSTB * 2 + ntp * 32) + offV;
                    ldmx4t(vh_s + voff, vbH);
                    ldmx4t(vl_s + voff, vbL);
#pragma unroll
                    for (int mt = 0; mt < 2; mt++) {
                        bf16mma(oacc[mt][2*ntp],   aEh[mt], vbH[0], vbH[1]);
                        bf16mma(oacc[mt][2*ntp],   aEh[mt], vbL[0], vbL[1]);
                        bf16mma(oacc[mt][2*ntp],   aEl[mt], vbH[0], vbH[1]);
                        bf16mma(oacc[mt][2*ntp+1], aEh[mt], vbH[2], vbH[3]);
                        bf16mma(oacc[mt][2*ntp+1], aEh[mt], vbL[2], vbL[3]);
                        bf16mma(oacc[mt][2*ntp+1], aEl[mt], vbH[2], vbH[3]);
                    }
                }
            }
        }
        __syncthreads();
    }

    float inv[4];
#pragma unroll
    for (int r = 0; r < 4; r++) {
        float s = lpa[r];
        s += __shfl_xor_sync(0xffffffffu, s, 1);
        s += __shfl_xor_sync(0xffffffffu, s, 2);
        inv[r] = 1.f / s;
    }
    if (qid == 0) {
#pragma unroll
        for (int mt = 0; mt < 2; mt++) {
            g_l[bh * Sc + i0 + r0w + mt*16 + gid]     = inv[mt*2];
            g_l[bh * Sc + i0 + r0w + mt*16 + gid + 8] = inv[mt*2 + 1];
        }
    }
    {
        float* ctx = g_ctx + ((size_t)b * Sc) * Ec + (size_t)h * Dc;
#pragma unroll
        for (int mt = 0; mt < 2; mt++) {
            const int row0 = i0 + r0w + mt * 16 + gid;
            const float iv0 = inv[mt*2], iv1 = inv[mt*2 + 1];
#pragma unroll
            for (int nt = 0; nt < 8; nt++) {
                const int col = nt * 8 + 2 * qid;
                float2 v0, v1;
                v0.x = oacc[mt][nt][0] * iv0; v0.y = oacc[mt][nt][1] * iv0;
                v1.x = oacc[mt][nt][2] * iv1; v1.y = oacc[mt][nt][3] * iv1;
                *(float2*)(ctx + (size_t)row0 * Ec + col) = v0;
                *(float2*)(ctx + (size_t)(row0 + 8) * Ec + col) = v1;
            }
        }
    }
}

// ---------------------------------------------------------------------------
// Attention PASS B (fork stream): 128 rows/block (2 CTAs/SM), warp owns
// 16 rows. Recompute S, write normalized attn + causal zero-fill.
// ---------------------------------------------------------------------------
__global__ void __launch_bounds__(256, 2) attn_passB(const int* __restrict__ isM,
                                                     float* __restrict__ attn_out)
{
    extern __shared__ char smraw[];
    const unsigned sbase = (unsigned)__cvta_generic_to_shared(smraw);
    const unsigned* Qs = (const unsigned*)(smraw);
    const unsigned* Ks = (const unsigned*)(smraw + OFFB_K);

    const int tid = threadIdx.x;
    const int masked = *isM;
    const int i0 = (masked ? (gridDim.x - 1 - blockIdx.x) : blockIdx.x) * 128;
    const int h  = blockIdx.y;
    const int b  = blockIdx.z;

    const int warp = tid >> 5, lane = tid & 31;
    const int gid = lane >> 2, qid = lane & 3;

    const size_t bh = (size_t)b * Hc + h;
    const float* Qg = g_qh + bh * Sc * Dc + (size_t)i0 * Dc;
    const float* Kg = g_kh + bh * Sc * Dc;

    const int jmax = masked ? (i0 + 128) : Sc;
    const int ntiles = jmax >> 7;

    // Q tile (128 x 64) + K0
#pragma unroll
    for (int t = 0; t < 8; t++) {
        const int c = tid + t * 256;
        const int row = c >> 4, col4 = (c & 15) * 4;
        cpasync16(sbase + (row * QSTf + col4) * 4, Qg + row * 64 + col4);
    }
#pragma unroll
    for (int t = 0; t < 8; t++) {
        const int c = tid + t * 256;
        const int row = c >> 4, col4 = (c & 15) * 4;
        cpasync16(sbase + OFFB_K + (row * KSTf + col4) * 4, Kg + row * 64 + col4);
    }
    CP_COMMIT();

    const int r0w = warp * 16;
    const int rmaxw = i0 + r0w + 15;

    const int row0 = i0 + r0w + gid;
    const int row1 = row0 + 8;
    float inv0 = g_l[bh * Sc + row0];
    float inv1 = g_l[bh * Sc + row1];

    for (int t = 0; t < ntiles; t++) {
        const int jt = t << 7;
        if (t + 1 < ntiles) {
            const float* Kn = Kg + (size_t)(jt + 128) * 64;
            const unsigned kb = OFFB_K + ((t + 1) & 1) * SZ_K1;
#pragma unroll
            for (int tt = 0; tt < 8; tt++) {
                const int c = tid + tt * 256;
                const int row = c >> 4, col4 = (c & 15) * 4;
                cpasync16(sbase + kb + (row * KSTf + col4) * 4, Kn + row * 64 + col4);
            }
            CP_COMMIT();
            CP_WAIT(1);
        } else {
            CP_WAIT(0);
        }
        __syncthreads();

        const unsigned* Kt = Ks + (t & 1) * (SZ_K1 / 4);

#pragma unroll
        for (int half = 0; half < 2; half++) {
            if (masked && (jt + half * 64) > rmaxw) {
                const float2 z = {0.f, 0.f};
#pragma unroll
                for (int nt = 0; nt < 8; nt++) {
                    const int jc = jt + half * 64 + nt * 8 + 2 * qid;
                    *(float2*)(attn_out + (bh * Sc + row0) * Sc + jc) = z;
                    *(float2*)(attn_out + (bh * Sc + row1) * Sc + jc) = z;
                }
                continue;
            }

            float sacc[8][4];
#pragma unroll
            for (int nt = 0; nt < 8; nt++)
#pragma unroll
                for (int e = 0; e < 4; e++) sacc[nt][e] = 0.f;

#pragma unroll
            for (int ks = 0; ks < 8; ks++) {
                unsigned qa[4];
                const unsigned* q0 = Qs + (r0w + gid) * QSTf + ks * 8;
                qa[0] = q0[qid];        qa[1] = q0[8 * QSTf + qid];
                qa[2] = q0[qid + 4];    qa[3] = q0[8 * QSTf + qid + 4];
#pragma unroll
                for (int nt = 0; nt < 8; nt++) {
                    const unsigned* kr = Kt + (half * 64 + nt * 8 + gid) * KSTf + ks * 8;
                    tf32mma(sacc[nt], qa, kr[qid], kr[qid + 4]);
                }
            }

#pragma unroll
            for (int nt = 0; nt < 8; nt++) {
                const int jc = jt + half * 64 + nt * 8 + 2 * qid;
                float s0 = sacc[nt][0], s1 = sacc[nt][1];
                float s2 = sacc[nt][2], s3 = sacc[nt][3];
                if (masked) {
                    if (jc     > row0) s0 = -1e9f;
                    if (jc + 1 > row0) s1 = -1e9f;
                    if (jc     > row1) s2 = -1e9f;
                    if (jc + 1 > row1) s3 = -1e9f;
                }
                float2 w0, w1;
                w0.x = __expf(s0) * inv0; w0.y = __expf(s1) * inv0;
                w1.x = __expf(s2) * inv1; w1.y = __expf(s3) * inv1;
                *(float2*)(attn_out + (bh * Sc + row0) * Sc + jc) = w0;
                *(float2*)(attn_out + (bh * Sc + row1) * Sc + jc) = w1;
            }
        }
        __syncthreads();
    }

    // zero-fill masked tail (j >= jmax)
    if (masked && jmax < Sc) {
        const int ncols = Sc - jmax;
        const float4 z = {0.f, 0.f, 0.f, 0.f};
        for (int r = warp; r < 128; r += 8) {
            float* rowp = attn_out + (bh * Sc + i0 + r) * Sc + jmax;
            for (int cz = lane * 4; cz < ncols; cz += 128)
                *(float4*)(rowp + cz) = z;
        }
    }
}

// ---------------------------------------------------------------------------
// Residual + LayerNorm
// ---------------------------------------------------------------------------
__global__ void __launch_bounds__(256) ln_kernel(const float* __restrict__ qin,
                                                 float* __restrict__ out)
{
    const size_t row = blockIdx.x;
    const int tid = threadIdx.x;
    float4 x  = *(const float4*)(g_tmp + row * 1024 + tid * 4);
    float4 qq = *(const float4*)(qin   + row * 1024 + tid * 4);
    x.x += qq.x; x.y += qq.y; x.z += qq.z; x.w += qq.w;

    float s  = x.x + x.y + x.z + x.w;
    float s2 = x.x*x.x + x.y*x.y + x.z*x.z + x.w*x.w;

    __shared__ float rs[8], rs2[8];
    const int w = tid >> 5, lane = tid & 31;
#pragma unroll
    for (int o = 16; o; o >>= 1) {
        s  += __shfl_xor_sync(0xffffffffu, s,  o);
        s2 += __shfl_xor_sync(0xffffffffu, s2, o);
    }
    if (!lane) { rs[w] = s; rs2[w] = s2; }
    __syncthreads();
    if (w == 0) {
        float a  = (lane < 8) ? rs[lane]  : 0.f;
        float a2 = (lane < 8) ? rs2[lane] : 0.f;
#pragma unroll
        for (int o = 4; o; o >>= 1) {
            a  += __shfl_xor_sync(0xffffffffu, a,  o);
            a2 += __shfl_xor_sync(0xffffffffu, a2, o);
        }
        if (!lane) { rs[0] = a; rs2[0] = a2; }
    }
    __syncthreads();
    const float mu   = rs[0] * (1.f / 1024.f);
    const float var  = rs2[0] * (1.f / 1024.f) - mu * mu;
    const float rstd = rsqrtf(var + 1e-5f);
    float4 o;
    o.x = (x.x - mu) * rstd; o.y = (x.y - mu) * rstd;
    o.z = (x.z - mu) * rstd; o.w = (x.w - mu) * rstd;
    *(float4*)(out + row * 1024 + tid * 4) = o;
}

// ---------------------------------------------------------------------------
extern "C" void kernel_launch(void* const* d_in, const int* in_sizes, int n_in,
                              void* d_out, int out_size)
{
    (void)in_sizes; (void)n_in; (void)out_size;
    const float* q  = (const float*)d_in[0];
    const float* k  = (const float*)d_in[1];
    const float* v  = (const float*)d_in[2];
    const float* Wq = (const float*)d_in[3];
    const float* bq = (const float*)d_in[4];
    const float* Wk = (const float*)d_in[5];
    const float* bk = (const float*)d_in[6];
    const float* Wv = (const float*)d_in[7];
    const float* bv = (const float*)d_in[8];
    const float* Wo = (const float*)d_in[9];
    const float* bo = (const float*)d_in[10];
    const int*   isM = (const int*)d_in[11];

    float* out  = (float*)d_out;
    float* attn = out + (size_t)Bc * Sc * Ec;

    cudaFuncSetAttribute(attn_passA,
                         cudaFuncAttributeMaxDynamicSharedMemorySize, ATTN_SMEM);
    cudaFuncSetAttribute(attn_passB,
                         cudaFuncAttributeMaxDynamicSharedMemorySize, ATTNB_SMEM);
    cudaFuncSetAttribute(gemm_qkv,
                         cudaFuncAttributeMaxDynamicSharedMemorySize, GEMM_SMEM);
    cudaFuncSetAttribute(gemm_out,
                         cudaFuncAttributeMaxDynamicSharedMemorySize, GEMM_SMEM);

    // fork-join resources (host objects, no device memory)
    cudaStream_t s2;
    cudaEvent_t e1, e2;
    cudaStreamCreateWithFlags(&s2, cudaStreamNonBlocking);
    cudaEventCreateWithFlags(&e1, cudaEventDisableTiming);
    cudaEventCreateWithFlags(&e2, cudaEventDisableTiming);

    dim3 gqkv(Ec / 128, M_TOT / 128, 3);
    gemm_qkv<<<gqkv, 256, GEMM_SMEM>>>(q, k, v, Wq, bq, Wk, bk, Wv, bv);

    attn_passA<<<dim3(Sc / 256, Hc, Bc), 256, ATTN_SMEM>>>(isM);

    // fork: passB (DRAM-bound) overlaps gemm_out + ln (tensor-bound)
    cudaEventRecord(e1, 0);
    cudaStreamWaitEvent(s2, e1, 0);
    attn_passB<<<dim3(Sc / 128, Hc, Bc), 256, ATTNB_SMEM, s2>>>(isM, attn);

    dim3 gg(Ec / 128, M_TOT / 128);
    gemm_out<<<gg, 256, GEMM_SMEM>>>(Wo, bo);
    ln_kernel<<<M_TOT, 256>>>(q, out);

    // join
    cudaEventRecord(e2, s2);
    cudaStreamWaitEvent(0, e2, 0);
}